// round 3
// baseline (speedup 1.0000x reference)
#include <cuda_runtime.h>
#include <cstdint>

// VQ-VAE bottleneck — reference-rounding-faithful, FFMA2 (fma.rn.f32x2) version.
// Each packed half-lane is a correctly-rounded FMA, so packing codeword pairs
// (k even -> lo, k odd -> hi) preserves the bit-exact sequential-over-c chain
// per codeword that round 2 validated (rel_err 4.8e-7).

#define NPOS   131072
#define CDIM   64
#define KCODES 512
#define HW     4096
#define NELEM  8388608
#define NPAIR  (KCODES / 2)

__device__ float g_loss_sum;

__global__ void vq_reset_kernel() { g_loss_sum = 0.0f; }

__global__ void vq_finalize_kernel(float* out, int loss_idx) {
    float L = g_loss_sum * (1.0f / (float)NELEM);
    out[loss_idx] = __fadd_rn(L, 0.25f * L);   // RN(L + RN(0.25*L))
}

__device__ __forceinline__ void fma2(unsigned long long& acc,
                                     unsigned long long a,
                                     unsigned long long b) {
    asm("fma.rn.f32x2 %0, %1, %2, %0;" : "+l"(acc) : "l"(a), "l"(b));
}

__device__ __forceinline__ unsigned long long pack2(float lo, float hi) {
    unsigned long long r;
    asm("mov.b64 %0, {%1, %2};" : "=l"(r) : "f"(lo), "f"(hi));
    return r;
}

__device__ __forceinline__ void unpack2(unsigned long long v, float& lo, float& hi) {
    asm("mov.b64 {%0, %1}, %2;" : "=f"(lo), "=f"(hi) : "l"(v));
}

// dynamic smem: pair-interleaved codebook [NPAIR][CDIM][2] + ||e_k||^2 [KCODES]
extern __shared__ float sm[];

__global__ __launch_bounds__(256, 1)
void vq_main_kernel(const float* __restrict__ x,
                    const float* __restrict__ cb,
                    float* __restrict__ out) {
    float* cbp  = sm;                      // 512*64 floats = 128 KB, pair-interleaved
    float* e2_s = sm + KCODES * CDIM;      // 512 floats

    // build pair-interleaved codebook: cbp[(p*CDIM + c)*2 + (k&1)] = cb[k][c]
    for (int i = threadIdx.x; i < KCODES * CDIM; i += blockDim.x) {
        int k = i >> 6, c = i & 63;
        cbp[(((k >> 1) * CDIM) + c) * 2 + (k & 1)] = cb[i];
    }

    // ||e_k||^2: sequential fp32, separate mul+add (ref order), from gmem (L1/L2 hot)
    for (int k = threadIdx.x; k < KCODES; k += blockDim.x) {
        float s = 0.0f;
        #pragma unroll
        for (int c = 0; c < CDIM; c++) {
            float e = cb[k * CDIM + c];
            s = __fadd_rn(s, __fmul_rn(e, e));
        }
        e2_s[k] = s;
    }
    __syncthreads();

    int p  = blockIdx.x * blockDim.x + threadIdx.x;   // 0..131071
    int b  = p >> 12;
    int hw = p & (HW - 1);

    // load z (coalesced per channel), pack broadcast pairs, compute ||z||^2 (ref order)
    const float* xp = x + (size_t)b * CDIM * HW + hw;
    unsigned long long zz[CDIM];
    float Z = 0.0f;
    #pragma unroll
    for (int c = 0; c < CDIM; c++) {
        float v = xp[(size_t)c * HW];
        zz[c] = pack2(v, v);
        Z = __fadd_rn(Z, __fmul_rn(v, v));
    }

    // argmin over 512 codewords: 4 pairs (8 codewords) in flight.
    // Each FFMA2 half-chain is sequential over c ascending (Eigen depth order).
    float bestd = 3.402823466e38f;
    int   best  = 0;
    const ulonglong2* cbp2 = (const ulonglong2*)cbp;   // [pair][c/2] -> (c, c+1)

    #pragma unroll 1
    for (int p0 = 0; p0 < NPAIR; p0 += 4) {
        unsigned long long m[4];
        m[0] = m[1] = m[2] = m[3] = 0ull;

        #pragma unroll
        for (int cp = 0; cp < CDIM / 2; cp++) {
            #pragma unroll
            for (int g = 0; g < 4; g++) {
                ulonglong2 e = cbp2[(p0 + g) * (CDIM / 2) + cp];  // LDS.128 broadcast
                fma2(m[g], zz[2 * cp],     e.x);
                fma2(m[g], zz[2 * cp + 1], e.y);
            }
        }

        #pragma unroll
        for (int g = 0; g < 4; g++) {
            float mlo, mhi;
            unpack2(m[g], mlo, mhi);
            int k = (p0 + g) * 2;
            float t0 = __fadd_rn(Z, e2_s[k]);
            float d0 = __fadd_rn(t0, -2.0f * mlo);
            if (d0 < bestd) { bestd = d0; best = k; }        // first-min wins
            float t1 = __fadd_rn(Z, e2_s[k + 1]);
            float d1 = __fadd_rn(t1, -2.0f * mhi);
            if (d1 < bestd) { bestd = d1; best = k + 1; }
        }
    }

    // straight-through output RN(x + RN(q - x)); accumulate ref SSE
    float* op = out + (size_t)b * CDIM * HW + hw;
    const float* bp = cbp + ((best >> 1) * CDIM) * 2 + (best & 1);
    float sse = 0.0f;
    #pragma unroll
    for (int c = 0; c < CDIM; c++) {
        float zl, zh;
        unpack2(zz[c], zl, zh);
        float q    = bp[2 * c];
        float diff = __fadd_rn(q, -zl);
        op[(size_t)c * HW] = __fadd_rn(zl, diff);
        sse = __fadd_rn(sse, __fmul_rn(diff, diff));
    }

    #pragma unroll
    for (int o = 16; o; o >>= 1) sse += __shfl_xor_sync(0xffffffffu, sse, o);
    if ((threadIdx.x & 31) == 0) atomicAdd(&g_loss_sum, sse);
}

extern "C" void kernel_launch(void* const* d_in, const int* in_sizes, int n_in,
                              void* d_out, int out_size) {
    const float* x   = (const float*)d_in[0];
    const float* cb  = (const float*)d_in[1];
    float*       out = (float*)d_out;

    const int smem_bytes = (KCODES * CDIM + KCODES) * (int)sizeof(float);  // 133120
    cudaFuncSetAttribute(vq_main_kernel,
                         cudaFuncAttributeMaxDynamicSharedMemorySize, smem_bytes);

    vq_reset_kernel<<<1, 1>>>();
    vq_main_kernel<<<NPOS / 256, 256, smem_bytes>>>(x, cb, out);
    if (out_size > NELEM)
        vq_finalize_kernel<<<1, 1>>>(out, out_size - 1);
}

// round 4
// speedup vs baseline: 1.0736x; 1.0736x over previous
#include <cuda_runtime.h>
#include <cstdint>

// VQ-VAE bottleneck — reference-rounding-faithful, FFMA2 with two POSITIONS
// packed per lane-pair (lo = position 2t, hi = position 2t+1).
// Each half-lane of fma.rn.f32x2 is a correctly-rounded fp32 FMA, and each
// position's chain stays strictly sequential over c ascending -> bit-exact to
// the round-2 emulation (rel_err 4.8e-7).
//
// Codebook held DUPLICATED in smem ((e_c,e_c) pairs) so the b-operand needs no
// packing; 256 KB total > smem, so two passes of 256 codewords (128 KB each).
// Single fused kernel: last-CTA-done counter computes the loss scalar.

#define NPOS    131072
#define CDIM    64
#define KCODES  512
#define HW      4096
#define NELEM   8388608
#define THREADS 256
#define POSPT   2
#define GRIDSZ  (NPOS / (THREADS * POSPT))   // 256
#define PASS_K  256                          // codewords per smem pass

__device__ float        g_loss_sum;   // zero-initialized
__device__ unsigned int g_done;       // zero-initialized

__device__ __forceinline__ void fma2_acc(unsigned long long& acc,
                                         unsigned long long a,
                                         unsigned long long b) {
    asm("fma.rn.f32x2 %0, %1, %2, %0;" : "+l"(acc) : "l"(a), "l"(b));
}
__device__ __forceinline__ unsigned long long fma2_v(unsigned long long a,
                                                     unsigned long long b,
                                                     unsigned long long c) {
    unsigned long long r;
    asm("fma.rn.f32x2 %0, %1, %2, %3;" : "=l"(r) : "l"(a), "l"(b), "l"(c));
    return r;
}
__device__ __forceinline__ unsigned long long add2_v(unsigned long long a,
                                                     unsigned long long b) {
    unsigned long long r;
    asm("add.rn.f32x2 %0, %1, %2;" : "=l"(r) : "l"(a), "l"(b));
    return r;
}
__device__ __forceinline__ unsigned long long pack2(float lo, float hi) {
    unsigned long long r;
    asm("mov.b64 %0, {%1, %2};" : "=l"(r) : "f"(lo), "f"(hi));
    return r;
}
__device__ __forceinline__ void unpack2(unsigned long long v, float& lo, float& hi) {
    asm("mov.b64 {%0, %1}, %2;" : "=f"(lo), "=f"(hi) : "l"(v));
}

// dynamic smem: duplicated codebook half [PASS_K][CDIM][2] + e2[KCODES]
extern __shared__ float sm[];

__global__ __launch_bounds__(THREADS, 1)
void vq_main_kernel(const float* __restrict__ x,
                    const float* __restrict__ cb,
                    float* __restrict__ out,
                    int loss_idx) {
    float* cbd = sm;                         // 256*64*2 floats = 128 KB
    float* e2s = sm + PASS_K * CDIM * 2;     // 512 floats
    const int tid = threadIdx.x;

    // ||e_k||^2 for all 512 k: sequential fp32, separate mul+add (ref order)
    for (int k = tid; k < KCODES; k += THREADS) {
        float s = 0.0f;
        #pragma unroll
        for (int c = 0; c < CDIM; c++) {
            float e = cb[k * CDIM + c];
            s = __fadd_rn(s, __fmul_rn(e, e));
        }
        e2s[k] = s;
    }

    // two adjacent positions per thread; adjacent hw -> one float2 gmem load/c
    const int p0 = (blockIdx.x * THREADS + tid) * 2;
    const int b  = p0 >> 12;
    const int hw = p0 & (HW - 1);            // even, so p0+1 stays in same b

    const float* xp = x + (size_t)b * CDIM * HW + hw;
    unsigned long long zz[CDIM];
    float Z0 = 0.0f, Z1 = 0.0f;
    #pragma unroll
    for (int c = 0; c < CDIM; c++) {
        float2 v = *(const float2*)(xp + (size_t)c * HW);
        zz[c] = pack2(v.x, v.y);
        Z0 = __fadd_rn(Z0, __fmul_rn(v.x, v.x));   // ref summation order
        Z1 = __fadd_rn(Z1, __fmul_rn(v.y, v.y));
    }
    const unsigned long long Zp   = pack2(Z0, Z1);
    const unsigned long long NEG2 = pack2(-2.0f, -2.0f);

    float bestd0 = 3.402823466e38f, bestd1 = 3.402823466e38f;
    int   best0 = 0, best1 = 0;

    #pragma unroll 1
    for (int kp = 0; kp < KCODES / PASS_K; kp++) {
        __syncthreads();    // previous pass fully consumed before overwrite
        // fill duplicated codebook half: cbd row k_local = [e0,e0,e1,e1,...]
        {
            const float* src = cb + kp * PASS_K * CDIM;
            float2*      dst = (float2*)cbd;
            for (int i = tid; i < PASS_K * CDIM; i += THREADS) {
                float v = src[i];
                dst[i] = make_float2(v, v);
            }
        }
        __syncthreads();

        const ulonglong2* cb2 = (const ulonglong2*)cbd;  // [k][cp] -> 2 dup pairs

        #pragma unroll 1
        for (int k0 = 0; k0 < PASS_K; k0 += 4) {
            unsigned long long m[4];
            m[0] = m[1] = m[2] = m[3] = 0ull;

            #pragma unroll
            for (int cp = 0; cp < CDIM / 2; cp++) {
                #pragma unroll
                for (int g = 0; g < 4; g++) {
                    ulonglong2 e = cb2[(k0 + g) * (CDIM / 2) + cp]; // LDS.128 bcast
                    fma2_acc(m[g], zz[2 * cp],     e.x);            // c ascending
                    fma2_acc(m[g], zz[2 * cp + 1], e.y);
                }
            }

            #pragma unroll
            for (int g = 0; g < 4; g++) {
                int   k   = kp * PASS_K + k0 + g;
                float e2  = e2s[k];
                unsigned long long t2 = add2_v(Zp, pack2(e2, e2)); // RN(Z+B)
                unsigned long long d2 = fma2_v(m[g], NEG2, t2);    // RN(t-2M)
                float d0, d1;
                unpack2(d2, d0, d1);
                if (d0 < bestd0) { bestd0 = d0; best0 = k; }   // first-min wins
                if (d1 < bestd1) { bestd1 = d1; best1 = k; }
            }
        }
    }

    // straight-through outputs RN(x + RN(q - x)) for both positions + SSE
    float* op = out + (size_t)b * CDIM * HW + hw;
    const float* q0p = cb + (size_t)best0 * CDIM;
    const float* q1p = cb + (size_t)best1 * CDIM;
    float sse = 0.0f;
    #pragma unroll 8
    for (int c = 0; c < CDIM; c++) {
        float z0, z1;
        unpack2(zz[c], z0, z1);
        float q0 = __ldg(q0p + c);
        float q1 = __ldg(q1p + c);
        float f0 = __fadd_rn(q0, -z0);
        float f1 = __fadd_rn(q1, -z1);
        float2 o;
        o.x = __fadd_rn(z0, f0);
        o.y = __fadd_rn(z1, f1);
        *(float2*)(op + (size_t)c * HW) = o;
        sse = __fadd_rn(sse, __fmul_rn(f0, f0));
        sse = __fadd_rn(sse, __fmul_rn(f1, f1));
    }

    #pragma unroll
    for (int o = 16; o; o >>= 1) sse += __shfl_xor_sync(0xffffffffu, sse, o);
    if ((tid & 31) == 0) atomicAdd(&g_loss_sum, sse);

    // fused finalize: last CTA computes loss, then resets for next graph replay
    __syncthreads();
    if (tid == 0) {
        __threadfence();
        unsigned t = atomicAdd(&g_done, 1u);
        if (t == gridDim.x - 1) {
            float L = atomicAdd(&g_loss_sum, 0.0f) * (1.0f / (float)NELEM);
            if (loss_idx >= 0)
                out[loss_idx] = __fadd_rn(L, 0.25f * L);  // RN(L + RN(0.25L))
            g_loss_sum = 0.0f;
            g_done     = 0u;
            __threadfence();
        }
    }
}

extern "C" void kernel_launch(void* const* d_in, const int* in_sizes, int n_in,
                              void* d_out, int out_size) {
    const float* x   = (const float*)d_in[0];
    const float* cb  = (const float*)d_in[1];
    float*       out = (float*)d_out;

    const int smem_bytes = (PASS_K * CDIM * 2 + KCODES) * (int)sizeof(float); // 133120
    cudaFuncSetAttribute(vq_main_kernel,
                         cudaFuncAttributeMaxDynamicSharedMemorySize, smem_bytes);

    int loss_idx = (out_size > NELEM) ? (out_size - 1) : -1;
    vq_main_kernel<<<GRIDSZ, THREADS, smem_bytes>>>(x, cb, out, loss_idx);
}

// round 5
// speedup vs baseline: 1.4281x; 1.3303x over previous
#include <cuda_runtime.h>
#include <cstdint>

// VQ-VAE bottleneck — register-tiled, reference-rounding-faithful.
// CTA: 512 positions, 256 threads (8 warps). Warp w owns k in [64w, 64w+64).
// Lane tile: 8 position-pairs x 8 codewords = 64 FFMA2 accumulators.
// z tile in smem [c][512]; e warp-uniform from gmem (L1) + register dup.
// Distances: d = RN( RN(Z + ||e_k||^2) - 2*(z.e_k) ), dot = sequential FMA
// over c ascending (validated bit-exact in rounds 2/4, rel_err ~2e-7).
// Argmin via u64 key (d_bits<<32)|k : numeric min == (d,k) lexicographic
// == jnp.argmin first-occurrence. Cross-warp merge: smem atomicMin.

#define NPOS    131072
#define CDIM    64
#define KCODES  512
#define HW      4096
#define NELEM   8388608
#define THREADS 256
#define P_CTA   512
#define GRIDSZ  (NPOS / P_CTA)        // 256

__device__ float        g_loss_sum;   // zero-initialized
__device__ unsigned int g_done;       // zero-initialized

typedef unsigned long long u64;

__device__ __forceinline__ void fma2_acc(u64& acc, u64 a, u64 b) {
    asm("fma.rn.f32x2 %0, %1, %2, %0;" : "+l"(acc) : "l"(a), "l"(b));
}
__device__ __forceinline__ u64 fma2_v(u64 a, u64 b, u64 c) {
    u64 r; asm("fma.rn.f32x2 %0, %1, %2, %3;" : "=l"(r) : "l"(a), "l"(b), "l"(c));
    return r;
}
__device__ __forceinline__ u64 add2_v(u64 a, u64 b) {
    u64 r; asm("add.rn.f32x2 %0, %1, %2;" : "=l"(r) : "l"(a), "l"(b));
    return r;
}
__device__ __forceinline__ u64 pack2(float lo, float hi) {
    u64 r; asm("mov.b64 %0, {%1, %2};" : "=l"(r) : "f"(lo), "f"(hi));
    return r;
}
__device__ __forceinline__ void unpack2(u64 v, float& lo, float& hi) {
    asm("mov.b64 {%0, %1}, %2;" : "=f"(lo), "=f"(hi) : "l"(v));
}

// smem: zs[64][512] (128KB) + Zs[512] + e2s[512] + bestArr[512] u64
extern __shared__ float sm[];

__global__ __launch_bounds__(THREADS, 1)
void vq_main_kernel(const float* __restrict__ x,
                    const float* __restrict__ cb,
                    float* __restrict__ out,
                    int loss_idx) {
    float* zs      = sm;                         // [c][512]
    float* Zs      = sm + CDIM * P_CTA;          // [512]
    float* e2s     = Zs + P_CTA;                 // [512]
    u64*   bestArr = (u64*)(e2s + KCODES);       // [512]

    const int tid  = threadIdx.x;
    const int w    = tid >> 5;
    const int lane = tid & 31;

    const int b   = blockIdx.x >> 3;             // 8 CTAs per batch image
    const int hw0 = (blockIdx.x & 7) * P_CTA;
    const float* xrow = x + (size_t)b * CDIM * HW + hw0;

    // ---- fill z tile (coalesced float4), init bestArr ----
    for (int q = tid; q < CDIM * (P_CTA / 4); q += THREADS) {
        int c  = q >> 7;                         // 128 float4 per row
        int p4 = (q & 127) << 2;
        float4 v = *(const float4*)(xrow + (size_t)c * HW + p4);
        *(float4*)(zs + c * P_CTA + p4) = v;
    }
    for (int p = tid; p < P_CTA; p += THREADS)
        bestArr[p] = 0xFFFFFFFFFFFFFFFFull;
    // ||e_k||^2, ref order (sequential mul+add)
    for (int k = tid; k < KCODES; k += THREADS) {
        float s = 0.0f;
        const float* ek = cb + k * CDIM;
        #pragma unroll
        for (int c = 0; c < CDIM; c++)
            s = __fadd_rn(s, __fmul_rn(ek[c], ek[c]));
        e2s[k] = s;
    }
    __syncthreads();

    // ---- ||z||^2 per position, ref order (needs zs ready) ----
    for (int p = tid; p < P_CTA; p += THREADS) {
        float s = 0.0f;
        #pragma unroll
        for (int c = 0; c < CDIM; c++) {
            float zv = zs[c * P_CTA + p];        // lanes consecutive: no conflict
            s = __fadd_rn(s, __fmul_rn(zv, zv));
        }
        Zs[p] = s;
    }
    __syncthreads();

    // ---- main: warp w covers k in [64w, 64w+64), 8-k tiles ----
    const u64 NEG2 = pack2(-2.0f, -2.0f);
    u64 bk[8][2];                                // best key per (pair, half)
    #pragma unroll
    for (int j = 0; j < 8; j++) bk[j][0] = bk[j][1] = 0xFFFFFFFFFFFFFFFFull;

    #pragma unroll 1
    for (int t = 0; t < 8; t++) {
        const int k0 = w * 64 + t * 8;
        const float* ep = cb + (size_t)k0 * CDIM;

        u64 acc[8][8];
        #pragma unroll
        for (int j = 0; j < 8; j++)
            #pragma unroll
            for (int i = 0; i < 8; i++) acc[j][i] = 0ull;

        #pragma unroll 4
        for (int c = 0; c < CDIM; c++) {
            u64 ed[8];
            #pragma unroll
            for (int i = 0; i < 8; i++) {        // warp-uniform LDG, L1-hot
                float e = __ldg(ep + i * CDIM + c);
                ed[i] = pack2(e, e);
            }
            const float* zc = zs + c * P_CTA + 2 * lane;
            #pragma unroll
            for (int j = 0; j < 8; j++) {
                u64 zp = *(const u64*)(zc + j * 64);   // LDS.64, conflict-free
                #pragma unroll
                for (int i = 0; i < 8; i++)
                    fma2_acc(acc[j][i], zp, ed[i]);    // c ascending per chain
            }
        }

        // epilogue: distances + key-min updates
        #pragma unroll
        for (int j = 0; j < 8; j++) {
            u64 Zp = *(const u64*)(Zs + 2 * (j * 32 + lane));
            #pragma unroll
            for (int i = 0; i < 8; i++) {
                float e2v = e2s[k0 + i];
                u64 t2 = add2_v(Zp, pack2(e2v, e2v));  // RN(Z + B)
                u64 d2 = fma2_v(acc[j][i], NEG2, t2);  // RN(t - 2M)
                float d0, d1;
                unpack2(d2, d0, d1);
                u64 key0 = ((u64)__float_as_uint(d0) << 32) | (unsigned)(k0 + i);
                u64 key1 = ((u64)__float_as_uint(d1) << 32) | (unsigned)(k0 + i);
                if (key0 < bk[j][0]) bk[j][0] = key0;
                if (key1 < bk[j][1]) bk[j][1] = key1;
            }
        }
    }

    // ---- cross-warp merge ----
    #pragma unroll
    for (int j = 0; j < 8; j++) {
        int p = 2 * (j * 32 + lane);
        atomicMin(&bestArr[p],     bk[j][0]);
        atomicMin(&bestArr[p + 1], bk[j][1]);
    }
    __syncthreads();

    // ---- output: thread handles positions tid and tid+256 ----
    float sse = 0.0f;
    #pragma unroll
    for (int h = 0; h < 2; h++) {
        int p = tid + h * 256;
        int kbest = (int)(bestArr[p] & 0x1FFu);
        const float* qk = cb + (size_t)kbest * CDIM;
        float* op = out + (size_t)b * CDIM * HW + hw0 + p;
        #pragma unroll 8
        for (int c = 0; c < CDIM; c++) {
            float zv   = zs[c * P_CTA + p];
            float qv   = __ldg(qk + c);
            float diff = __fadd_rn(qv, -zv);           // RN(q - x)
            op[(size_t)c * HW] = __fadd_rn(zv, diff);  // RN(x + RN(q - x))
            sse = __fadd_rn(sse, __fmul_rn(diff, diff));
        }
    }

    #pragma unroll
    for (int o = 16; o; o >>= 1) sse += __shfl_xor_sync(0xffffffffu, sse, o);
    if (lane == 0) atomicAdd(&g_loss_sum, sse);

    // ---- fused finalize (loss scalar), reset for next graph replay ----
    __syncthreads();
    if (tid == 0) {
        __threadfence();
        unsigned done = atomicAdd(&g_done, 1u);
        if (done == gridDim.x - 1) {
            float L = atomicAdd(&g_loss_sum, 0.0f) * (1.0f / (float)NELEM);
            if (loss_idx >= 0)
                out[loss_idx] = __fadd_rn(L, 0.25f * L);   // RN(L + RN(0.25L))
            g_loss_sum = 0.0f;
            g_done     = 0u;
            __threadfence();
        }
    }
}

extern "C" void kernel_launch(void* const* d_in, const int* in_sizes, int n_in,
                              void* d_out, int out_size) {
    const float* x   = (const float*)d_in[0];
    const float* cb  = (const float*)d_in[1];
    float*       out = (float*)d_out;

    const int smem_bytes = (CDIM * P_CTA + P_CTA + KCODES) * (int)sizeof(float)
                         + P_CTA * (int)sizeof(u64);   // 128K + 2K + 2K + 4K
    cudaFuncSetAttribute(vq_main_kernel,
                         cudaFuncAttributeMaxDynamicSharedMemorySize, smem_bytes);

    int loss_idx = (out_size > NELEM) ? (out_size - 1) : -1;
    vq_main_kernel<<<GRIDSZ, THREADS, smem_bytes>>>(x, cb, out, loss_idx);
}